// round 15
// baseline (speedup 1.0000x reference)
#include <cuda_runtime.h>
#include <cuda_bf16.h>
#include <cstdint>

#define BATCH 512
#define SEQ   2048
#define NT    48          // NUM_TAGS
#define WPB   4           // warps (= chains) per block, one per SMSP
#define TPB   (WPB * 32)
#define BIAS  4.5f

typedef unsigned long long u64;

__device__ float g_part[BATCH];
__device__ float g_score[BATCH];

__device__ __forceinline__ u64 pack2(float lo, float hi) {
    u64 r; asm("mov.b64 %0, {%1, %2};" : "=l"(r) : "f"(lo), "f"(hi)); return r;
}
__device__ __forceinline__ void unpack2(u64 v, float& lo, float& hi) {
    asm("mov.b64 {%0, %1}, %2;" : "=f"(lo), "=f"(hi) : "l"(v));
}
__device__ __forceinline__ u64 fma2(u64 a, u64 b, u64 c) {
    u64 d;
    asm("fma.rn.f32x2 %0, %1, %2, %3;" : "=l"(d) : "l"(a), "l"(b), "l"(c));
    return d;
}
__device__ __forceinline__ u64 add2(u64 a, u64 b) {
    u64 d;
    asm("add.rn.f32x2 %0, %1, %2;" : "=l"(d) : "l"(a), "l"(b));
    return d;
}
__device__ __forceinline__ float ex2f(float x) {
    float r; asm("ex2.approx.f32 %0, %1;" : "=f"(r) : "f"(x)); return r;
}

#define L2E   1.4426950408889634f
#define NBL2E (-BIAS * 1.4426950408889634f)

// One WARP per chain, 4 independent warps (chains) per block -> each warp on
// its own SMSP (wid % 4), 128 blocks -> 1 CTA/SM, 1 chain-warp per SMSP.
// No __syncthreads in the loop; each warp is fully warp-synchronous.
// Lane j (<24) owns output tags (2j, 2j+1); expT for both owned columns lives
// in 48 packed f32x2 registers. u[48] ping-pongs through this warp's private
// smem, read back as 12x ld.shared.v2.b64 broadcasts.
__global__ void __launch_bounds__(TPB, 1)
crf_forward(const float* __restrict__ em,      // [B,S,48]
            const float* __restrict__ trans,   // [48,48]
            const float* __restrict__ startt,  // [48]
            const float* __restrict__ endt,    // [48]
            const int*   __restrict__ tags,    // [B,S]
            const float* __restrict__ mask)    // [B,S]
{
    const int tid = threadIdx.x;
    const int w   = tid >> 5;             // warp = chain slot 0..3
    const int j   = tid & 31;             // lane
    const int b   = blockIdx.x * WPB + w; // chain id
    const bool act = (j < NT / 2);        // 24 active lanes
    const int t0  = 2 * j;
    const int t1  = 2 * j + 1;

    __shared__ __align__(16) float ubuf[WPB][2][NT];
    __shared__ float tsh[NT * NT];        // raw transitions (path score)

    // expT rows packed over i-pairs, one array per owned output tag.
    u64 M0[NT / 2], M1[NT / 2];
    #pragma unroll
    for (int q = 0; q < NT / 2; q++) {
        float a0 = act ? __expf(trans[(2 * q)     * NT + t0]) : 0.0f;
        float a1 = act ? __expf(trans[(2 * q + 1) * NT + t0]) : 0.0f;
        float b0 = act ? __expf(trans[(2 * q)     * NT + t1]) : 0.0f;
        float b1 = act ? __expf(trans[(2 * q + 1) * NT + t1]) : 0.0f;
        M0[q] = pack2(a0, a1);
        M1[q] = pack2(b0, b1);
    }
    for (int k = tid; k < NT * NT; k += TPB) tsh[k] = trans[k];
    __syncthreads();                       // once: tsh visible to all warps

    const float* emb = em   + (size_t)b * SEQ * NT;
    const int*   tgb = tags + (size_t)b * SEQ;
    const float* mkb = mask + (size_t)b * SEQ;

    // ---- t = 0 init ----
    float e0x = 0.0f, e0y = 0.0f, u0 = 0.0f, u1 = 0.0f;
    if (act) {
        float2 e0 = *(const float2*)(emb + t0);
        e0x = e0.x; e0y = e0.y;
        u0 = __expf(startt[t0] + e0x);
        u1 = __expf(startt[t1] + e0y);
    }
    float s = 0.0f;

    const int tag0 = tgb[0];
    float scorep = 0.0f;
    if (j == (tag0 >> 1))
        scorep = startt[tag0] + ((tag0 & 1) ? e0y : e0x);
    int   prev = tag0;
    float msum = mkb[0];

    uint32_t ua = (uint32_t)__cvta_generic_to_shared(&ubuf[w][0][0]);
    uint32_t ub = (uint32_t)__cvta_generic_to_shared(&ubuf[w][1][0]);
    if (act) asm volatile("st.shared.b64 [%0], %1;" :: "r"(ua + j * 8), "l"(pack2(u0, u1)));
    __syncwarp();

    const float EXP_NEG_BIAS = __expf(-BIAS);

#define CRF_STEP(EV2, MM, TG)                                                 \
    do {                                                                      \
        u64 b0=0ull,b1=0ull,b2=0ull,b3=0ull;                                  \
        u64 c0=0ull,c1=0ull,c2=0ull,c3=0ull;                                  \
        _Pragma("unroll")                                                     \
        for (int q = 0; q < 12; q++) {                                        \
            u64 pA, pB;                                                       \
            asm volatile("ld.shared.v2.b64 {%0, %1}, [%2];"                   \
                         : "=l"(pA), "=l"(pB) : "r"(ua + q * 16));            \
            if ((q & 1) == 0) {                                               \
                b0 = fma2(pA, M0[2*q], b0);  b1 = fma2(pB, M0[2*q+1], b1);    \
                c0 = fma2(pA, M1[2*q], c0);  c1 = fma2(pB, M1[2*q+1], c1);    \
            } else {                                                          \
                b2 = fma2(pA, M0[2*q], b2);  b3 = fma2(pB, M0[2*q+1], b3);    \
                c2 = fma2(pA, M1[2*q], c2);  c3 = fma2(pB, M1[2*q+1], c3);    \
            }                                                                 \
        }                                                                     \
        u64 bs = add2(add2(b0, b1), add2(b2, b3));                            \
        u64 cs = add2(add2(c0, c1), add2(c2, c3));                            \
        float w0l, w0h, w1l, w1h;                                             \
        unpack2(bs, w0l, w0h);  unpack2(cs, w1l, w1h);                        \
        float w0 = w0l + w0h, w1 = w1l + w1h;                                 \
        float evx, evy;  unpack2((EV2), evx, evy);                            \
        float un0 = w0 * ex2f(fmaf(evx, L2E, NBL2E));                         \
        float un1 = w1 * ex2f(fmaf(evy, L2E, NBL2E));                         \
        bool  mm  = ((MM) != 0.0f);                                           \
        u0 = mm ? un0 : (u0 * EXP_NEG_BIAS);                                  \
        u1 = mm ? un1 : (u1 * EXP_NEG_BIAS);                                  \
        s += BIAS;                                                            \
        if (j == ((TG) >> 1))                                                 \
            scorep += (tsh[prev * NT + (TG)] + (((TG) & 1) ? evy : evx)) * (MM); \
        prev  = (TG);                                                         \
        msum += (MM);                                                         \
        if (act) asm volatile("st.shared.b64 [%0], %1;"                       \
                              :: "r"(ub + j * 8), "l"(pack2(u0, u1)));        \
        __syncwarp();                                                         \
        { uint32_t tt_ = ua; ua = ub; ub = tt_; }                             \
    } while (0)

#define PREFETCH(EVA, MA, TA, TT0)                                            \
    do {                                                                      \
        _Pragma("unroll")                                                     \
        for (int k = 0; k < 8; k++) {                                         \
            int tt = (TT0) + k;                                               \
            tt = (tt < SEQ) ? tt : (SEQ - 1);                                 \
            if (act) {                                                        \
                float2 e_ = __ldg((const float2*)(emb + (size_t)tt * NT + t0)); \
                (EVA)[k] = pack2(e_.x, e_.y);                                 \
            } else (EVA)[k] = 0ull;                                           \
            (MA)[k] = __ldg(&mkb[tt]);                                        \
            (TA)[k] = __ldg(&tgb[tt]);                                        \
        }                                                                     \
    } while (0)

#define RESCALE()                                                             \
    do {                                                                      \
        float x_ = fmaxf(u0, u1);                                             \
        _Pragma("unroll")                                                     \
        for (int o = 16; o > 0; o >>= 1)                                      \
            x_ = fmaxf(x_, __shfl_xor_sync(0xffffffffu, x_, o));              \
        if (x_ > 0.0f) {                                                      \
            float inv_ = 1.0f / x_;                                           \
            u0 *= inv_;  u1 *= inv_;                                          \
            s += __logf(x_);                                                  \
        }                                                                     \
        if (act) asm volatile("st.shared.b64 [%0], %1;"                       \
                              :: "r"(ua + j * 8), "l"(pack2(u0, u1)));        \
        __syncwarp();                                                         \
    } while (0)

    // ---- prefetch buffers (ping-pong) ----
    u64 evA[8], evB[8];
    float mA[8], mB[8];
    int   tA[8], tB[8];

    PREFETCH(evA, mA, tA, 1);          // t = 1..8

    // ---- main loop: 127 groups of 16 steps (t = 1..2032) ----
    #pragma unroll 1
    for (int g = 0; g < 127; g++) {
        const int base = 1 + g * 16;

        PREFETCH(evB, mB, tB, base + 8);
        #pragma unroll
        for (int k = 0; k < 8; k++) CRF_STEP(evA[k], mA[k], tA[k]);

        PREFETCH(evA, mA, tA, base + 16);
        #pragma unroll
        for (int k = 0; k < 8; k++) CRF_STEP(evB[k], mB[k], tB[k]);

        RESCALE();                      // every 16 steps
    }

    // ---- tail: t = 2033..2047 (15 steps) ----
    PREFETCH(evB, mB, tB, 2041);
    #pragma unroll
    for (int k = 0; k < 8; k++) CRF_STEP(evA[k], mA[k], tA[k]);   // 2033..2040
    #pragma unroll
    for (int k = 0; k < 7; k++) CRF_STEP(evB[k], mB[k], tB[k]);   // 2041..2047

#undef CRF_STEP
#undef PREFETCH
#undef RESCALE

    // ---- epilogue: warp-local reductions ----
    float y  = 0.0f;
    if (act) y = u0 * __expf(endt[t0]) + u1 * __expf(endt[t1]);
    float sc = scorep;
    #pragma unroll
    for (int o = 16; o > 0; o >>= 1) {
        y  += __shfl_xor_sync(0xffffffffu, y,  o);
        sc += __shfl_xor_sync(0xffffffffu, sc, o);
    }
    if (j == 0) {
        g_part[b] = __logf(y) + s;

        int last_idx = (int)(msum + 0.5f) - 1;
        last_idx = max(0, min(SEQ - 1, last_idx));
        int ltag = tgb[last_idx];
        g_score[b] = sc + endt[ltag];
    }
}

// out[0] = mean(partition - score) = -mean(score - partition)
__global__ void crf_finalize(float* __restrict__ out)
{
    const int i = threadIdx.x;            // 512 threads
    float v = g_part[i] - g_score[i];
    __shared__ float sh[16];
    #pragma unroll
    for (int o = 16; o > 0; o >>= 1)
        v += __shfl_xor_sync(0xffffffffu, v, o);
    if ((i & 31) == 0) sh[i >> 5] = v;
    __syncthreads();
    if (i < 16) {
        float x = sh[i];
        #pragma unroll
        for (int o = 8; o > 0; o >>= 1)
            x += __shfl_xor_sync(0x0000ffffu, x, o);
        if (i == 0) out[0] = x * (1.0f / (float)BATCH);
    }
}

extern "C" void kernel_launch(void* const* d_in, const int* in_sizes, int n_in,
                              void* d_out, int out_size)
{
    const float* em     = (const float*)d_in[0];  // emissions [512,2048,48]
    const float* trans  = (const float*)d_in[1];  // transitions [48,48]
    const float* startt = (const float*)d_in[2];  // start_transitions [48]
    const float* endt   = (const float*)d_in[3];  // end_transitions [48]
    const int*   tags   = (const int*)  d_in[4];  // tags [512,2048]
    const float* mask   = (const float*)d_in[5];  // mask [512,2048]
    float* out = (float*)d_out;

    crf_forward<<<BATCH / WPB, TPB>>>(em, trans, startt, endt, tags, mask);
    crf_finalize<<<1, BATCH>>>(out);
}

// round 16
// speedup vs baseline: 1.2712x; 1.2712x over previous
#include <cuda_runtime.h>
#include <cuda_bf16.h>
#include <cstdint>

#define BATCH 512
#define SEQ   2048
#define NT    48          // NUM_TAGS
#define NTP   64          // padded lanes per chain (2 warps)
#define CPB   2           // chains per block
#define TPB   (CPB * NTP) // 128 threads, 4 warps -> all 4 SMSPs
#define BIAS  4.5f

typedef unsigned long long u64;

__device__ float g_part[BATCH];
__device__ float g_score[BATCH];

__device__ __forceinline__ u64 pack2(float lo, float hi) {
    u64 r; asm("mov.b64 %0, {%1, %2};" : "=l"(r) : "f"(lo), "f"(hi)); return r;
}
__device__ __forceinline__ void unpack2(u64 v, float& lo, float& hi) {
    asm("mov.b64 {%0, %1}, %2;" : "=f"(lo), "=f"(hi) : "l"(v));
}
__device__ __forceinline__ u64 fma2(u64 a, u64 b, u64 c) {
    u64 d;
    asm("fma.rn.f32x2 %0, %1, %2, %3;" : "=l"(d) : "l"(a), "l"(b), "l"(c));
    return d;
}
__device__ __forceinline__ float ex2f(float x) {
    float r; asm("ex2.approx.f32 %0, %1;" : "=f"(r) : "f"(x)); return r;
}

#define L2E   1.4426950408889634f
#define NBL2E (-BIAS * 1.4426950408889634f)

// 128-thread block = 2 INDEPENDENT chains.
//   chain 0: threads 0..63  (warps 0,1 -> SMSPs 0,1)
//   chain 1: threads 64..127(warps 2,3 -> SMSPs 2,3)
// Each chain synchronizes ONLY its own 2 warps via a named barrier
// (bar.sync c+1, 64), so the two chains interleave freely and hide each
// other's latency on their SMSP pair. No block-wide barrier in the loop.
// Per chain: thread jj (<48) owns output tag jj; linear-domain forward
//   u' = (u . expT[:,jj]) * exp(emit - BIAS), s += BIAS
// Dot: 12x ld.shared.v2.b64 broadcast + 24 fma.rn.f32x2 (4 accumulators).
// 8-step double-buffered register prefetch; max-rescale every 16 steps.
__global__ void __launch_bounds__(TPB, 2)
crf_forward(const float* __restrict__ em,      // [B,S,48]
            const float* __restrict__ trans,   // [48,48]
            const float* __restrict__ startt,  // [48]
            const float* __restrict__ endt,    // [48]
            const int*   __restrict__ tags,    // [B,S]
            const float* __restrict__ mask)    // [B,S]
{
    const int tid  = threadIdx.x;         // 0..127
    const int c    = tid >> 6;            // chain within block (0/1)
    const int jj   = tid & (NTP - 1);     // 0..63 within chain
    const int lane = tid & 31;
    const int wrp2 = (tid >> 5) & 1;      // warp within chain (0/1)
    const int b    = blockIdx.x * CPB + c;
    const int barid = c + 1;              // named barrier id for this chain

    __shared__ __align__(16) float ubuf[CPB][2][NTP];
    __shared__ float tsh[NT * NT];        // raw transitions (path score)
    __shared__ float red[CPB][2];
    __shared__ float red2[CPB][4];

    const bool act = (jj < NT);

    // expT column jj packed into 24 f32x2 registers (zeros for padded lanes)
    u64 M2[NT / 2];
    #pragma unroll
    for (int k = 0; k < NT / 2; k++) {
        float lo = act ? __expf(trans[(2 * k)     * NT + jj]) : 0.0f;
        float hi = act ? __expf(trans[(2 * k + 1) * NT + jj]) : 0.0f;
        M2[k] = pack2(lo, hi);
    }
    for (int k = tid; k < NT * NT; k += TPB) tsh[k] = trans[k];

    const float* emb = em   + (size_t)b * SEQ * NT;
    const int*   tgb = tags + (size_t)b * SEQ;
    const float* mkb = mask + (size_t)b * SEQ;

    // ---- t = 0 init ----
    float e0 = act ? emb[jj] : 0.0f;
    float u  = act ? __expf(startt[jj] + e0) : 0.0f;
    float s  = 0.0f;

    const int tag0 = tgb[0];
    float scorep = (jj == tag0) ? (startt[jj] + e0) : 0.0f;
    int   prev   = tag0;
    float msum   = mkb[0];

    uint32_t ua = (uint32_t)__cvta_generic_to_shared(&ubuf[c][0][0]);
    uint32_t ub = (uint32_t)__cvta_generic_to_shared(&ubuf[c][1][0]);
    ubuf[c][0][jj] = u;
    __syncthreads();                       // once: tsh + initial u visible

    const float EXP_NEG_BIAS = __expf(-BIAS);

#define CHAIN_BAR() asm volatile("bar.sync %0, %1;" :: "r"(barid), "n"(NTP) : "memory")

#define CRF_STEP(EV, MM, TG)                                                  \
    do {                                                                      \
        u64 a0 = 0ull, a1 = 0ull, a2 = 0ull, a3 = 0ull;                       \
        _Pragma("unroll")                                                     \
        for (int q = 0; q < 12; q++) {                                        \
            u64 p0, p1;                                                       \
            asm volatile("ld.shared.v2.b64 {%0, %1}, [%2];"                   \
                         : "=l"(p0), "=l"(p1) : "r"(ua + q * 16));            \
            if ((q & 1) == 0) { a0 = fma2(p0, M2[2*q],   a0);                 \
                                a1 = fma2(p1, M2[2*q+1], a1); }               \
            else              { a2 = fma2(p0, M2[2*q],   a2);                 \
                                a3 = fma2(p1, M2[2*q+1], a3); }               \
        }                                                                     \
        float l0,h0,l1,h1,l2,h2,l3,h3;                                        \
        unpack2(a0,l0,h0); unpack2(a1,l1,h1);                                 \
        unpack2(a2,l2,h2); unpack2(a3,l3,h3);                                 \
        float w = ((l0+h0)+(l1+h1)) + ((l2+h2)+(l3+h3));                      \
        float unew = w * ex2f(fmaf((EV), L2E, NBL2E));                        \
        u = ((MM) != 0.0f) ? unew : (u * EXP_NEG_BIAS);                       \
        s += BIAS;                                                            \
        if (jj == (TG)) scorep += (tsh[prev * NT + jj] + (EV)) * (MM);        \
        prev  = (TG);                                                         \
        msum += (MM);                                                         \
        if (act) asm volatile("st.shared.b32 [%0], %1;"                       \
                              :: "r"(ub + jj * 4), "f"(u));                   \
        CHAIN_BAR();                                                          \
        { uint32_t sw_ = ua; ua = ub; ub = sw_; }                             \
    } while (0)

#define PREFETCH(EVA, MA, TA, TT0)                                            \
    do {                                                                      \
        _Pragma("unroll")                                                     \
        for (int k = 0; k < 8; k++) {                                         \
            int tt = (TT0) + k;                                               \
            tt = (tt < SEQ) ? tt : (SEQ - 1);                                 \
            (EVA)[k] = act ? __ldg(&emb[(size_t)tt * NT + jj]) : 0.0f;        \
            (MA)[k]  = __ldg(&mkb[tt]);                                       \
            (TA)[k]  = __ldg(&tgb[tt]);                                       \
        }                                                                     \
    } while (0)

    // ---- prefetch buffers (ping-pong) ----
    float evA[8], evB[8];
    float mA[8],  mB[8];
    int   tA[8],  tB[8];

    PREFETCH(evA, mA, tA, 1);          // t = 1..8

    // ---- main loop: 127 groups of 16 steps (t = 1..2032) ----
    #pragma unroll 1
    for (int g = 0; g < 127; g++) {
        const int base = 1 + g * 16;

        PREFETCH(evB, mB, tB, base + 8);
        #pragma unroll
        for (int k = 0; k < 8; k++) CRF_STEP(evA[k], mA[k], tA[k]);

        PREFETCH(evA, mA, tA, base + 16);
        #pragma unroll
        for (int k = 0; k < 8; k++) CRF_STEP(evB[k], mB[k], tB[k]);

        // ---- rescale every 16 steps (chain-local) ----
        {
            float x = u;
            #pragma unroll
            for (int o = 16; o > 0; o >>= 1)
                x = fmaxf(x, __shfl_xor_sync(0xffffffffu, x, o));
            if (lane == 0) red[c][wrp2] = x;
            CHAIN_BAR();
            float mx = fmaxf(red[c][0], red[c][1]);
            if (mx > 0.0f) {
                u *= (1.0f / mx);
                s += __logf(mx);
            }
            if (act) asm volatile("st.shared.b32 [%0], %1;"
                                  :: "r"(ua + jj * 4), "f"(u));
            CHAIN_BAR();
        }
    }

    // ---- tail: t = 2033..2047 (15 steps) ----
    PREFETCH(evB, mB, tB, 2041);
    #pragma unroll
    for (int k = 0; k < 8; k++) CRF_STEP(evA[k], mA[k], tA[k]);   // 2033..2040
    #pragma unroll
    for (int k = 0; k < 7; k++) CRF_STEP(evB[k], mB[k], tB[k]);   // 2041..2047

#undef CRF_STEP
#undef PREFETCH

    // ---- epilogue: reduce partition + score across the chain's 2 warps ----
    float y  = act ? (u * __expf(endt[jj])) : 0.0f;
    float sc = scorep;
    #pragma unroll
    for (int o = 16; o > 0; o >>= 1) {
        y  += __shfl_xor_sync(0xffffffffu, y,  o);
        sc += __shfl_xor_sync(0xffffffffu, sc, o);
    }
    if (lane == 0) { red2[c][wrp2] = y; red2[c][2 + wrp2] = sc; }
    CHAIN_BAR();
    if (jj == 0) {
        float tot = red2[c][0] + red2[c][1];
        g_part[b] = __logf(tot) + s;

        int last_idx = (int)(msum + 0.5f) - 1;
        last_idx = max(0, min(SEQ - 1, last_idx));
        int ltag = tgb[last_idx];
        g_score[b] = (red2[c][2] + red2[c][3]) + endt[ltag];
    }
#undef CHAIN_BAR
}

// out[0] = mean(partition - score) = -mean(score - partition)
__global__ void crf_finalize(float* __restrict__ out)
{
    const int i = threadIdx.x;            // 512 threads
    float v = g_part[i] - g_score[i];
    __shared__ float sh[16];
    #pragma unroll
    for (int o = 16; o > 0; o >>= 1)
        v += __shfl_xor_sync(0xffffffffu, v, o);
    if ((i & 31) == 0) sh[i >> 5] = v;
    __syncthreads();
    if (i < 16) {
        float x = sh[i];
        #pragma unroll
        for (int o = 8; o > 0; o >>= 1)
            x += __shfl_xor_sync(0x0000ffffu, x, o);
        if (i == 0) out[0] = x * (1.0f / (float)BATCH);
    }
}

extern "C" void kernel_launch(void* const* d_in, const int* in_sizes, int n_in,
                              void* d_out, int out_size)
{
    const float* em     = (const float*)d_in[0];  // emissions [512,2048,48]
    const float* trans  = (const float*)d_in[1];  // transitions [48,48]
    const float* startt = (const float*)d_in[2];  // start_transitions [48]
    const float* endt   = (const float*)d_in[3];  // end_transitions [48]
    const int*   tags   = (const int*)  d_in[4];  // tags [512,2048]
    const float* mask   = (const float*)d_in[5];  // mask [512,2048]
    float* out = (float*)d_out;

    crf_forward<<<BATCH / CPB, TPB>>>(em, trans, startt, endt, tags, mask);
    crf_finalize<<<1, BATCH>>>(out);
}